// round 7
// baseline (speedup 1.0000x reference)
#include <cuda_runtime.h>
#include <math.h>

// ChamferLoss: B=8, N=M=4096, D=3 — sorted-bin pruned NN search.

#define BATCH   8
#define NPTS    4096
#define NCLOUD  16                 // 8 batches x {pred, targ}
#define NBINS   128
#define XMIN    (-3.2f)
#define XSPAN   6.4f
#define BINW    (XSPAN / NBINS)    // 0.05
#define INV_BINW ((float)NBINS / XSPAN)

#define S_THREADS 256
#define WPB       (S_THREADS / 32)               // 8 warps/block
#define TOTAL_WARPS (NCLOUD * (NPTS / 32))       // 2048
#define S_BLOCKS  (TOTAL_WARPS / WPB)            // 256

__device__ float4 g_sorted[NCLOUD][NPTS];        // (x,y,z,|t|^2), bin-grouped by x
__device__ int    g_binstart[NCLOUD][NBINS + 1];
__device__ double g_sum  = 0.0;
__device__ unsigned int g_tick = 0;

static __device__ __forceinline__ int bin_of(float x) {
    int b = (int)((x - XMIN) * INV_BINW);
    return min(max(b, 0), NBINS - 1);
}

// ---------------- Kernel 1: counting-sort each cloud into x-bins ----------------
__global__ __launch_bounds__(256) void bin_kernel(
    const float* __restrict__ pred,
    const float* __restrict__ targ)
{
    __shared__ int cnt[NBINS];
    __shared__ int ofs[NBINS];

    const int c = blockIdx.x;                 // cloud 0..15
    const int b = c >> 1;
    const float* __restrict__ src = ((c & 1) ? targ : pred) + (size_t)b * NPTS * 3;

    for (int k = threadIdx.x; k < NBINS; k += blockDim.x) cnt[k] = 0;
    __syncthreads();

    for (int i = threadIdx.x; i < NPTS; i += blockDim.x)
        atomicAdd(&cnt[bin_of(src[3 * i])], 1);
    __syncthreads();

    if (threadIdx.x == 0) {
        int s = 0;
        for (int k = 0; k < NBINS; k++) {
            ofs[k] = s;
            g_binstart[c][k] = s;
            s += cnt[k];
        }
        g_binstart[c][NBINS] = s;   // == NPTS
        if (c == 0) { g_sum = 0.0; g_tick = 0; }   // runs before search kernel
    }
    __syncthreads();

    for (int i = threadIdx.x; i < NPTS; i += blockDim.x) {
        float x = src[3 * i + 0];
        float y = src[3 * i + 1];
        float z = src[3 * i + 2];
        float w = fmaf(x, x, fmaf(y, y, z * z));
        int pos = atomicAdd(&ofs[bin_of(x)], 1);
        g_sorted[c][pos] = make_float4(x, y, z, w);
    }
}

// ---------------- Kernel 2: warp-coherent pruned NN search ----------------
__global__ __launch_bounds__(S_THREADS) void search_kernel(float* __restrict__ out)
{
    __shared__ float warpsums[WPB];

    const int lane = threadIdx.x & 31;
    const int wid  = threadIdx.x >> 5;
    const int wg   = blockIdx.x * WPB + wid;        // 0..2047
    const int combo = wg >> 7;                      // 0..15  (b, dir)
    const int wi    = wg & 127;                     // warp within cloud
    const int b     = combo >> 1;
    const int dir   = combo & 1;
    const int cs    = b * 2 + dir;                  // source cloud
    const int ct    = b * 2 + (dir ^ 1);            // target cloud

    const float4* __restrict__ tgt = g_sorted[ct];
    const int*    __restrict__ bst = g_binstart[ct];

    // This lane's source point (sorted order -> warp is x-coherent)
    const float4 p = g_sorted[cs][wi * 32 + lane];
    const float mx = -2.0f * p.x;
    const float my = -2.0f * p.y;
    const float mz = -2.0f * p.z;
    const float p2 = p.w;

    // Warp's initial bin range
    int mybin = bin_of(p.x);
    int lo = mybin, hi = mybin;
    #pragma unroll
    for (int o = 16; o > 0; o >>= 1) {
        lo = min(lo, __shfl_xor_sync(0xFFFFFFFFu, lo, o));
        hi = max(hi, __shfl_xor_sync(0xFFFFFFFFu, hi, o));
    }

    float best = INFINITY;     // min of (|t|^2 - 2 p.t); true d2 = best + p2

    // Process bins [blo, bhi] inclusive
    auto process = [&](int bin) {
        int s = bst[bin], e = bst[bin + 1];
        #pragma unroll 2
        for (int j = s; j < e; j++) {
            float4 t = tgt[j];      // all lanes same addr -> broadcast, L1-resident
            float v = fmaf(mx, t.x, fmaf(my, t.y, fmaf(mz, t.z, t.w)));
            best = fminf(best, v);
        }
    };

    for (int k = lo; k <= hi; k++) process(k);

    // Expand while any lane's bound crosses the current edge
    while (true) {
        float bd2 = best + p2;                          // current best true d2
        float dl  = p.x - (XMIN + lo * BINW);           // >= 0 (lo <= bin(px))
        float dr  = (XMIN + (hi + 1) * BINW) - p.x;
        bool nl = (lo > 0)         && (dl * dl < bd2);
        bool nr = (hi < NBINS - 1) && (dr * dr < bd2);
        unsigned ml = __ballot_sync(0xFFFFFFFFu, nl);
        unsigned mr = __ballot_sync(0xFFFFFFFFu, nr);
        if (!ml && !mr) break;
        if (ml) { lo--; process(lo); }
        if (mr) { hi++; process(hi); }
    }

    float d = sqrtf(fmaxf(best + p2, 0.0f));

    // Warp -> block -> global reduction
    float s = d;
    #pragma unroll
    for (int o = 16; o > 0; o >>= 1)
        s += __shfl_xor_sync(0xFFFFFFFFu, s, o);
    if (lane == 0) warpsums[wid] = s;
    __syncthreads();
    if (threadIdx.x == 0) {
        float v = 0.0f;
        #pragma unroll
        for (int k = 0; k < WPB; k++) v += warpsums[k];
        const double scale = 1.0 / ((double)BATCH * (double)NPTS);
        atomicAdd(&g_sum, (double)v * scale);
    }

    // Ticket: last block publishes the result
    __threadfence();
    __shared__ unsigned int s_done;
    if (threadIdx.x == 0) s_done = atomicAdd(&g_tick, 1u);
    __syncthreads();
    if (s_done == S_BLOCKS - 1 && threadIdx.x == 0) {
        double total = atomicAdd(&g_sum, 0.0);   // atomic read
        out[0] = (float)total;
        g_tick = 0;                               // g_sum re-zeroed by bin_kernel next replay
    }
}

extern "C" void kernel_launch(void* const* d_in, const int* in_sizes, int n_in,
                              void* d_out, int out_size) {
    const float* pred = (const float*)d_in[0];
    const float* targ = (const float*)d_in[1];
    float* out = (float*)d_out;

    bin_kernel<<<NCLOUD, 256>>>(pred, targ);
    search_kernel<<<S_BLOCKS, S_THREADS>>>(out);
}

// round 8
// speedup vs baseline: 2.3623x; 2.3623x over previous
#include <cuda_runtime.h>
#include <math.h>

// ChamferLoss: B=8, N=M=4096, D=3 — fused block-local bin-sort + pruned NN.

#define BATCH    8
#define NPTS     4096
#define NBINS    128
#define XMIN     (-3.2f)
#define BINW     0.05f
#define INV_BINW 20.0f
#define THREADS  512
#define SLICES   8                         // source slices per combo
#define NCOMBO   16                        // 8 batches x 2 directions
#define NBLOCKS  (NCOMBO * SLICES)         // 128
#define SRCPB    (NPTS / SLICES)           // 512 sources per block
#define NWARPS   (THREADS / 32)

__device__ double       g_sum  = 0.0;
__device__ unsigned int g_tick = 0;

struct Smem {
    float4 tgt[NPTS];          // 64 KB  bin-sorted target cloud (x,y,z,|t|^2)
    float4 srcp[SRCPB];        //  8 KB  block-local sorted source slice
    int    bst[NBINS + 1];     // target bin prefix (persists through search)
    int    ofs[NBINS];         // working offsets / source prefix
    int    cnt[NBINS];
    float  warpsums[NWARPS];
    unsigned int s_done;
};

static __device__ __forceinline__ int bin_of(float x) {
    int b = (int)((x - XMIN) * INV_BINW);
    return min(max(b, 0), NBINS - 1);
}

// Warp 0: exclusive prefix of cnt[] -> ofs[] (and optionally bst[] + total)
static __device__ __forceinline__ void scan_bins(Smem* s, bool to_bst) {
    const int lane = threadIdx.x;
    int c0 = s->cnt[lane * 4 + 0], c1 = s->cnt[lane * 4 + 1];
    int c2 = s->cnt[lane * 4 + 2], c3 = s->cnt[lane * 4 + 3];
    int tot = c0 + c1 + c2 + c3;
    int pre = tot;
    #pragma unroll
    for (int o = 1; o < 32; o <<= 1) {
        int n = __shfl_up_sync(0xFFFFFFFFu, pre, o);
        if (lane >= o) pre += n;
    }
    pre -= tot;                       // exclusive
    int p0 = pre, p1 = pre + c0, p2 = p1 + c1, p3 = p2 + c2;
    s->ofs[lane * 4 + 0] = p0; s->ofs[lane * 4 + 1] = p1;
    s->ofs[lane * 4 + 2] = p2; s->ofs[lane * 4 + 3] = p3;
    if (to_bst) {
        s->bst[lane * 4 + 0] = p0; s->bst[lane * 4 + 1] = p1;
        s->bst[lane * 4 + 2] = p2; s->bst[lane * 4 + 3] = p3;
        if (lane == 31) s->bst[NBINS] = p3 + c3;
    }
}

__global__ __launch_bounds__(THREADS) void chamfer_kernel(
    const float* __restrict__ pred,
    const float* __restrict__ targ,
    float* __restrict__ out)
{
    extern __shared__ char smem_raw[];
    Smem* s = (Smem*)smem_raw;
    const int tid = threadIdx.x;

    const int combo = blockIdx.x / SLICES;
    const int slice = blockIdx.x % SLICES;
    const int dir   = combo & 1;
    const int b     = combo >> 1;
    const float* __restrict__ sp = (dir == 0 ? pred : targ) + (size_t)b * NPTS * 3;
    const float* __restrict__ tp = (dir == 0 ? targ : pred) + (size_t)b * NPTS * 3;

    // ---- Stage 1: bin-sort full target cloud into smem ----
    for (int k = tid; k < NBINS; k += THREADS) s->cnt[k] = 0;
    __syncthreads();
    #pragma unroll
    for (int i = tid; i < NPTS; i += THREADS)
        atomicAdd(&s->cnt[bin_of(tp[3 * i])], 1);
    __syncthreads();
    if (tid < 32) scan_bins(s, true);
    __syncthreads();
    #pragma unroll
    for (int i = tid; i < NPTS; i += THREADS) {
        float x = tp[3 * i + 0], y = tp[3 * i + 1], z = tp[3 * i + 2];
        float w = fmaf(x, x, fmaf(y, y, z * z));
        int pos = atomicAdd(&s->ofs[bin_of(x)], 1);
        s->tgt[pos] = make_float4(x, y, z, w);
    }
    __syncthreads();

    // ---- Stage 2: block-local bin-sort of this block's 512 sources ----
    for (int k = tid; k < NBINS; k += THREADS) s->cnt[k] = 0;
    __syncthreads();
    {
        const int i = slice * SRCPB + tid;       // SRCPB == THREADS
        atomicAdd(&s->cnt[bin_of(sp[3 * i])], 1);
    }
    __syncthreads();
    if (tid < 32) scan_bins(s, false);
    __syncthreads();
    {
        const int i = slice * SRCPB + tid;
        float x = sp[3 * i + 0], y = sp[3 * i + 1], z = sp[3 * i + 2];
        float w = fmaf(x, x, fmaf(y, y, z * z));
        int pos = atomicAdd(&s->ofs[bin_of(x)], 1);
        s->srcp[pos] = make_float4(x, y, z, w);
    }
    __syncthreads();

    // ---- Stage 3: two-phase pruned NN search (per thread, ballot-free) ----
    const float4 p = s->srcp[tid];
    const float mx = -2.0f * p.x, my = -2.0f * p.y, mz = -2.0f * p.z;
    const float p2 = p.w;

    float best = INFINITY;          // min of (|t|^2 - 2 p.t); d2 = best + p2

    // Phase A: own bin (expand window only while empty — rare)
    const int b0 = bin_of(p.x);
    int lo = b0, hi = b0;
    int sA = s->bst[lo], eA = s->bst[hi + 1];
    while (sA == eA) {
        lo = max(lo - 1, 0);
        hi = min(hi + 1, NBINS - 1);
        sA = s->bst[lo]; eA = s->bst[hi + 1];
    }
    #pragma unroll 4
    for (int j = sA; j < eA; j++) {
        float4 t = s->tgt[j];
        float v = fmaf(mx, t.x, fmaf(my, t.y, fmaf(mz, t.z, t.w)));
        best = fminf(best, v);
    }

    // Phase B: one flat scan over the conservative final range
    float bd2  = fmaxf(best + p2, 0.0f);
    float dcur = sqrtf(bd2) * 1.0001f + 1e-6f;
    int klo = min(max((int)floorf((p.x - dcur - XMIN) * INV_BINW), 0), NBINS - 1);
    int khi = min(max((int)floorf((p.x + dcur - XMIN) * INV_BINW), 0), NBINS - 1);
    int sB = s->bst[klo], eB = s->bst[khi + 1];
    #pragma unroll 4
    for (int j = sB; j < eB; j++) {
        float4 t = s->tgt[j];
        float v = fmaf(mx, t.x, fmaf(my, t.y, fmaf(mz, t.z, t.w)));
        best = fminf(best, v);
    }

    float d = sqrtf(fmaxf(best + p2, 0.0f));

    // ---- Reduction ----
    float acc = d;
    #pragma unroll
    for (int o = 16; o > 0; o >>= 1)
        acc += __shfl_xor_sync(0xFFFFFFFFu, acc, o);
    const int lane = tid & 31, wid = tid >> 5;
    if (lane == 0) s->warpsums[wid] = acc;
    __syncthreads();
    if (tid == 0) {
        float v = 0.0f;
        #pragma unroll
        for (int k = 0; k < NWARPS; k++) v += s->warpsums[k];
        atomicAdd(&g_sum, (double)v / ((double)BATCH * (double)NPTS));
    }

    // ---- Ticket: last block publishes + resets ----
    __threadfence();
    if (tid == 0) s->s_done = atomicAdd(&g_tick, 1u);
    __syncthreads();
    if (s->s_done == NBLOCKS - 1 && tid == 0) {
        double total = atomicAdd(&g_sum, 0.0);   // atomic read
        out[0] = (float)total;
        g_sum  = 0.0;
        g_tick = 0;
    }
}

extern "C" void kernel_launch(void* const* d_in, const int* in_sizes, int n_in,
                              void* d_out, int out_size) {
    const float* pred = (const float*)d_in[0];
    const float* targ = (const float*)d_in[1];
    float* out = (float*)d_out;

    static bool attr_set = false;
    if (!attr_set) {
        cudaFuncSetAttribute(chamfer_kernel,
                             cudaFuncAttributeMaxDynamicSharedMemorySize,
                             (int)sizeof(Smem));
        attr_set = true;
    }
    chamfer_kernel<<<NBLOCKS, THREADS, sizeof(Smem)>>>(pred, targ, out);
}

// round 9
// speedup vs baseline: 5.1560x; 2.1827x over previous
#include <cuda_runtime.h>
#include <math.h>

// ChamferLoss: B=8, N=M=4096, D=3 — block-local bin-sort + warp-uniform pruned NN.

#define BATCH    8
#define NPTS     4096
#define NBINS    128
#define XMIN     (-3.2f)
#define BINW     0.05f
#define INV_BINW 20.0f
#define THREADS  256
#define SLICES   16                        // source slices per combo
#define NCOMBO   16                        // 8 batches x 2 directions
#define NBLOCKS  (NCOMBO * SLICES)         // 256
#define SRCPB    (NPTS / SLICES)           // 256 sources per block (== THREADS)
#define NWARPS   (THREADS / 32)

__device__ double       g_sum  = 0.0;
__device__ unsigned int g_tick = 0;

struct Smem {
    float4 tgt[NPTS];          // 64 KB  bin-sorted target cloud (x,y,z,|t|^2)
    float4 srcp[SRCPB];        //  4 KB  block-local sorted source slice
    int    bst[NBINS + 1];     // target bin prefix
    int    ofs[NBINS];
    int    cnt[NBINS];
    float  warpsums[NWARPS];
    unsigned int s_done;
};

static __device__ __forceinline__ int bin_of(float x) {
    int b = (int)((x - XMIN) * INV_BINW);
    return min(max(b, 0), NBINS - 1);
}

// Warp 0: exclusive prefix of cnt[] -> ofs[] (and optionally bst[])
static __device__ __forceinline__ void scan_bins(Smem* s, bool to_bst) {
    const int lane = threadIdx.x;
    int c0 = s->cnt[lane * 4 + 0], c1 = s->cnt[lane * 4 + 1];
    int c2 = s->cnt[lane * 4 + 2], c3 = s->cnt[lane * 4 + 3];
    int tot = c0 + c1 + c2 + c3;
    int pre = tot;
    #pragma unroll
    for (int o = 1; o < 32; o <<= 1) {
        int n = __shfl_up_sync(0xFFFFFFFFu, pre, o);
        if (lane >= o) pre += n;
    }
    pre -= tot;                       // exclusive
    int p0 = pre, p1 = pre + c0, p2 = p1 + c1, p3 = p2 + c2;
    s->ofs[lane * 4 + 0] = p0; s->ofs[lane * 4 + 1] = p1;
    s->ofs[lane * 4 + 2] = p2; s->ofs[lane * 4 + 3] = p3;
    if (to_bst) {
        s->bst[lane * 4 + 0] = p0; s->bst[lane * 4 + 1] = p1;
        s->bst[lane * 4 + 2] = p2; s->bst[lane * 4 + 3] = p3;
        if (lane == 31) s->bst[NBINS] = p3 + c3;
    }
}

__global__ __launch_bounds__(THREADS) void chamfer_kernel(
    const float* __restrict__ pred,
    const float* __restrict__ targ,
    float* __restrict__ out)
{
    extern __shared__ char smem_raw[];
    Smem* s = (Smem*)smem_raw;
    const int tid = threadIdx.x;

    const int combo = blockIdx.x / SLICES;
    const int slice = blockIdx.x % SLICES;
    const int dir   = combo & 1;
    const int b     = combo >> 1;
    const float* __restrict__ sp = (dir == 0 ? pred : targ) + (size_t)b * NPTS * 3;
    const float* __restrict__ tp = (dir == 0 ? targ : pred) + (size_t)b * NPTS * 3;

    // ---- Stage 1: bin-sort full target cloud into smem ----
    for (int k = tid; k < NBINS; k += THREADS) s->cnt[k] = 0;
    __syncthreads();
    #pragma unroll
    for (int i = tid; i < NPTS; i += THREADS)
        atomicAdd(&s->cnt[bin_of(tp[3 * i])], 1);
    __syncthreads();
    if (tid < 32) scan_bins(s, true);
    __syncthreads();
    #pragma unroll
    for (int i = tid; i < NPTS; i += THREADS) {
        float x = tp[3 * i + 0], y = tp[3 * i + 1], z = tp[3 * i + 2];
        float w = fmaf(x, x, fmaf(y, y, z * z));
        int pos = atomicAdd(&s->ofs[bin_of(x)], 1);
        s->tgt[pos] = make_float4(x, y, z, w);
    }
    __syncthreads();

    // ---- Stage 2: block-local bin-sort of this block's 256 sources ----
    for (int k = tid; k < NBINS; k += THREADS) s->cnt[k] = 0;
    __syncthreads();
    {
        const int i = slice * SRCPB + tid;       // SRCPB == THREADS
        atomicAdd(&s->cnt[bin_of(sp[3 * i])], 1);
    }
    __syncthreads();
    if (tid < 32) scan_bins(s, false);
    __syncthreads();
    {
        const int i = slice * SRCPB + tid;
        float x = sp[3 * i + 0], y = sp[3 * i + 1], z = sp[3 * i + 2];
        float w = fmaf(x, x, fmaf(y, y, z * z));
        int pos = atomicAdd(&s->ofs[bin_of(x)], 1);
        s->srcp[pos] = make_float4(x, y, z, w);
    }
    __syncthreads();

    // ---- Stage 3: warp-uniform two-phase pruned NN search ----
    const float4 p = s->srcp[tid];      // warp lanes are x-adjacent (sorted)
    const float mx = -2.0f * p.x, my = -2.0f * p.y, mz = -2.0f * p.z;
    const float p2 = p.w;

    float best = INFINITY;              // min of (|t|^2 - 2 p.t); d2 = best + p2

    // Phase A: warp-union own-bin range (uniform across the warp)
    int blo = bin_of(p.x), bhi = blo;
    #pragma unroll
    for (int o = 16; o > 0; o >>= 1) {
        blo = min(blo, __shfl_xor_sync(0xFFFFFFFFu, blo, o));
        bhi = max(bhi, __shfl_xor_sync(0xFFFFFFFFu, bhi, o));
    }
    int sA = s->bst[blo], eA = s->bst[bhi + 1];
    while (sA == eA) {                  // rare: expand uniformly until non-empty
        blo = max(blo - 1, 0);
        bhi = min(bhi + 1, NBINS - 1);
        sA = s->bst[blo]; eA = s->bst[bhi + 1];
    }
    #pragma unroll 4
    for (int j = sA; j < eA; j++) {     // broadcast LDS: all lanes same address
        float4 t = s->tgt[j];
        float v = fmaf(mx, t.x, fmaf(my, t.y, fmaf(mz, t.z, t.w)));
        best = fminf(best, v);
    }

    // Phase B: warp-union conservative final range; scan only the new segments
    float dcur = sqrtf(fmaxf(best + p2, 0.0f)) * 1.0001f + 1e-6f;
    int klo = min(max((int)floorf((p.x - dcur - XMIN) * INV_BINW), 0), NBINS - 1);
    int khi = min(max((int)floorf((p.x + dcur - XMIN) * INV_BINW), 0), NBINS - 1);
    #pragma unroll
    for (int o = 16; o > 0; o >>= 1) {
        klo = min(klo, __shfl_xor_sync(0xFFFFFFFFu, klo, o));
        khi = max(khi, __shfl_xor_sync(0xFFFFFFFFu, khi, o));
    }
    klo = min(klo, blo);                // ranges must nest for segment split
    khi = max(khi, bhi);
    int sB = s->bst[klo], eB = s->bst[khi + 1];
    #pragma unroll 4
    for (int j = sB; j < sA; j++) {     // left delta
        float4 t = s->tgt[j];
        float v = fmaf(mx, t.x, fmaf(my, t.y, fmaf(mz, t.z, t.w)));
        best = fminf(best, v);
    }
    #pragma unroll 4
    for (int j = eA; j < eB; j++) {     // right delta
        float4 t = s->tgt[j];
        float v = fmaf(mx, t.x, fmaf(my, t.y, fmaf(mz, t.z, t.w)));
        best = fminf(best, v);
    }

    float d = sqrtf(fmaxf(best + p2, 0.0f));

    // ---- Reduction ----
    float acc = d;
    #pragma unroll
    for (int o = 16; o > 0; o >>= 1)
        acc += __shfl_xor_sync(0xFFFFFFFFu, acc, o);
    const int lane = tid & 31, wid = tid >> 5;
    if (lane == 0) s->warpsums[wid] = acc;
    __syncthreads();
    if (tid == 0) {
        float v = 0.0f;
        #pragma unroll
        for (int k = 0; k < NWARPS; k++) v += s->warpsums[k];
        atomicAdd(&g_sum, (double)v / ((double)BATCH * (double)NPTS));
    }

    // ---- Ticket: last block publishes + resets ----
    __threadfence();
    if (tid == 0) s->s_done = atomicAdd(&g_tick, 1u);
    __syncthreads();
    if (s->s_done == NBLOCKS - 1 && tid == 0) {
        double total = atomicAdd(&g_sum, 0.0);   // atomic read
        out[0] = (float)total;
        g_sum  = 0.0;
        g_tick = 0;
    }
}

extern "C" void kernel_launch(void* const* d_in, const int* in_sizes, int n_in,
                              void* d_out, int out_size) {
    const float* pred = (const float*)d_in[0];
    const float* targ = (const float*)d_in[1];
    float* out = (float*)d_out;

    static bool attr_set = false;
    if (!attr_set) {
        cudaFuncSetAttribute(chamfer_kernel,
                             cudaFuncAttributeMaxDynamicSharedMemorySize,
                             (int)sizeof(Smem));
        attr_set = true;
    }
    chamfer_kernel<<<NBLOCKS, THREADS, sizeof(Smem)>>>(pred, targ, out);
}